// round 7
// baseline (speedup 1.0000x reference)
#include <cuda_runtime.h>
#include <cstdint>

// RevNet additive coupling: y1 = x1 ; y2 = x2 + x1 @ W
// x rows: [x1(128) | x2(128)] fp32, W: 128x128 fp32, 262144 rows.
//
// R7: m16n8k8 TF32 HMMA, 1024 threads (32 warps, occ 50%). Warp tile
// 16 rows x 32 cols (16 acc regs). cp.async double-buffered x1, smem W^T.
// x2 read directly in epilogue (32 warps hide the latency). <=64 regs goal.

#define D 128
#define TILE_M 128
#define THREADS 1024
#define P 132   // padded smem row stride (floats) -> conflict-free fragments

static constexpr int ROWS_TOTAL = 262144;
static constexpr int NUM_TILES  = ROWS_TOTAL / TILE_M;   // 2048
static constexpr int WT_FLOATS  = D * P;                 // 16896
static constexpr int XB_FLOATS  = TILE_M * P;            // 16896
static constexpr int SMEM_BYTES = (WT_FLOATS + 2 * XB_FLOATS) * 4;  // 202752

__device__ __forceinline__ uint32_t f2tf32(float f) {
    uint32_t r;
    asm("cvt.rna.tf32.f32 %0, %1;" : "=r"(r) : "f"(f));
    return r;
}
__device__ __forceinline__ void cp16(void* smem_dst, const void* gsrc) {
    uint32_t s = (uint32_t)__cvta_generic_to_shared(smem_dst);
    asm volatile("cp.async.cg.shared.global [%0], [%1], 16;" :: "r"(s), "l"(gsrc));
}
__device__ __forceinline__ void mma_tf32(float& d0, float& d1, float& d2, float& d3,
                                         uint32_t a0, uint32_t a1, uint32_t a2, uint32_t a3,
                                         uint32_t b0, uint32_t b1) {
    asm volatile(
        "mma.sync.aligned.m16n8k8.row.col.f32.tf32.tf32.f32 "
        "{%0,%1,%2,%3}, {%4,%5,%6,%7}, {%8,%9}, {%0,%1,%2,%3};"
        : "+f"(d0), "+f"(d1), "+f"(d2), "+f"(d3)
        : "r"(a0), "r"(a1), "r"(a2), "r"(a3), "r"(b0), "r"(b1));
}

__global__ void __launch_bounds__(THREADS, 1)
revnet_hmma_kernel(const float* __restrict__ x,
                   const float* __restrict__ w,
                   float* __restrict__ out)
{
    extern __shared__ float smem[];
    uint32_t* Wt = (uint32_t*)smem;                        // [128 n][P] tf32
    float* xb[2] = { smem + WT_FLOATS, smem + WT_FLOATS + XB_FLOATS };

    const int tid   = threadIdx.x;
    const int wid   = tid >> 5;
    const int lane  = tid & 31;
    const int gid   = lane >> 2;          // 0..7
    const int tig   = lane & 3;           // 0..3
    const int slab  = (wid & 7) << 4;     // m-slab base row (0..112)
    const int nbase = (wid >> 3) << 5;    // n-quarter base col (0,32,64,96)

    // Stage W^T as tf32: Wt[n][k] = tf32(w[k][n]). One-time, coalesced LDG.
    for (int idx = tid; idx < D * D; idx += THREADS) {
        const int k = idx >> 7, n = idx & 127;
        Wt[n * P + k] = f2tf32(w[idx]);
    }

    // Async-load x1 of tile t into buffer b (fp32, padded rows).
    auto issue_tile = [&](int t, int b) {
        const long rowbase = (long)t * TILE_M;
        float* dst = xb[b];
        #pragma unroll
        for (int i = tid; i < TILE_M * (D / 4); i += THREADS) {
            const int r = i >> 5;
            const int q = i & 31;
            cp16(dst + r * P + 4 * q, x + (rowbase + r) * 256L + 4 * q);
        }
        asm volatile("cp.async.commit_group;");
    };

    const int start = blockIdx.x;
    if (start < NUM_TILES) issue_tile(start, 0);

    int buf = 0;
    for (int t = start; t < NUM_TILES; t += gridDim.x, buf ^= 1) {
        const int nxt = t + gridDim.x;
        if (nxt < NUM_TILES) {
            issue_tile(nxt, buf ^ 1);
            asm volatile("cp.async.wait_group 1;");
        } else {
            asm volatile("cp.async.wait_group 0;");
        }
        __syncthreads();   // current x1 buffer (and Wt on iter 0) visible

        const float* x1s = xb[buf];
        const long rowbase = (long)t * TILE_M;

        // y1 = x1: smem -> gmem, coalesced float4 (4 iters/thread).
        #pragma unroll
        for (int i = tid; i < TILE_M * (D / 4); i += THREADS) {
            const int r = i >> 5;
            const int q = i & 31;
            *(float4*)(out + (rowbase + r) * 256L + 4 * q) =
                *(const float4*)(x1s + r * P + 4 * q);
        }

        // Mainloop: 4 n-tiles per warp, 16 k-steps.
        float acc[4][4];
        #pragma unroll
        for (int n = 0; n < 4; n++)
            { acc[n][0] = 0.f; acc[n][1] = 0.f; acc[n][2] = 0.f; acc[n][3] = 0.f; }

        const float*    arow0 = x1s + (slab + gid) * P;
        const float*    arow1 = arow0 + 8 * P;
        const uint32_t* wtb   = Wt + (nbase + gid) * P + tig;

        #pragma unroll 4
        for (int ks = 0; ks < 16; ks++) {
            const int k0 = ks * 8 + tig;
            const uint32_t a0 = f2tf32(arow0[k0]);
            const uint32_t a1 = f2tf32(arow1[k0]);
            const uint32_t a2 = f2tf32(arow0[k0 + 4]);
            const uint32_t a3 = f2tf32(arow1[k0 + 4]);

            #pragma unroll
            for (int n = 0; n < 4; n++) {
                const uint32_t* bp = wtb + n * 8 * P + ks * 8;
                mma_tf32(acc[n][0], acc[n][1], acc[n][2], acc[n][3],
                         a0, a1, a2, a3, bp[0], bp[4]);
            }
        }

        // Epilogue: y2 = x2 + acc. Direct LDG.64 (sector-exact), 32 warps
        // interleave to hide the latency.
        const long r0 = rowbase + slab + gid;
        #pragma unroll
        for (int n = 0; n < 4; n++) {
            const long g0 = r0 * 256L + 128 + nbase + n * 8 + 2 * tig;
            const long g1 = g0 + 8 * 256L;
            const float2 x20 = *(const float2*)(x + g0);
            const float2 x21 = *(const float2*)(x + g1);
            float2 o0, o1;
            o0.x = x20.x + acc[n][0];
            o0.y = x20.y + acc[n][1];
            o1.x = x21.x + acc[n][2];
            o1.y = x21.y + acc[n][3];
            *(float2*)(out + g0) = o0;
            *(float2*)(out + g1) = o1;
        }

        __syncthreads();   // all smem reads done before buffer refill
    }
}

extern "C" void kernel_launch(void* const* d_in, const int* in_sizes, int n_in,
                              void* d_out, int out_size)
{
    const float* x = (const float*)d_in[0];   // [8, 32768, 256] fp32
    const float* w = (const float*)d_in[1];   // [128, 128] fp32
    float* out = (float*)d_out;

    cudaFuncSetAttribute(revnet_hmma_kernel,
                         cudaFuncAttributeMaxDynamicSharedMemorySize,
                         SMEM_BYTES);

    revnet_hmma_kernel<<<148, THREADS, SMEM_BYTES>>>(x, w, out);
}

// round 8
// speedup vs baseline: 1.3500x; 1.3500x over previous
#include <cuda_runtime.h>
#include <cstdint>

// RevNet additive coupling: y1 = x1 ; y2 = x2 + x1 @ W
// x rows: [x1(128) | x2(128)] fp32, W: 128x128 fp32, 262144 rows.
//
// R8: bf16 m16n8k16 HMMA, TWO independent 512-thread CTAs per SM (decoupled
// pipelines), fused loader (LDG fp32 -> STG y1 + cvt -> STS bf16) prefetched
// one tile ahead in registers, x2 prefetched to registers. 64-row tiles.

#define D 128
#define TILE_M 64
#define THREADS 512
#define SA 68    // X2 (bf16-pair words) row stride
#define SB 136   // W2 (bf16-pair words) row stride

static constexpr int ROWS_TOTAL = 262144;
static constexpr int NUM_TILES  = ROWS_TOTAL / TILE_M;    // 4096
static constexpr int W2_WORDS   = 64 * SB;                // 8704
static constexpr int XB_WORDS   = TILE_M * SA;            // 4352
static constexpr int SMEM_BYTES = (W2_WORDS + 2 * XB_WORDS) * 4;  // 69632

__device__ __forceinline__ uint32_t bfpack(float lo, float hi) {
    uint32_t r;
    asm("cvt.rn.bf16x2.f32 %0, %1, %2;" : "=r"(r) : "f"(hi), "f"(lo));
    return r;
}
__device__ __forceinline__ void mma_bf16(float& d0, float& d1, float& d2, float& d3,
                                         uint32_t a0, uint32_t a1, uint32_t a2, uint32_t a3,
                                         uint32_t b0, uint32_t b1) {
    asm volatile(
        "mma.sync.aligned.m16n8k16.row.col.f32.bf16.bf16.f32 "
        "{%0,%1,%2,%3}, {%4,%5,%6,%7}, {%8,%9}, {%0,%1,%2,%3};"
        : "+f"(d0), "+f"(d1), "+f"(d2), "+f"(d3)
        : "r"(a0), "r"(a1), "r"(a2), "r"(a3), "r"(b0), "r"(b1));
}

__global__ void __launch_bounds__(THREADS, 2)
revnet_bf16_kernel(const float* __restrict__ x,
                   const float* __restrict__ w,
                   float* __restrict__ out)
{
    extern __shared__ uint32_t smem[];
    uint32_t* W2 = smem;                             // [64 kp][SB]: {W[2kp][n], W[2kp+1][n]}
    uint32_t* XB[2] = { smem + W2_WORDS, smem + W2_WORDS + XB_WORDS };

    const int tid  = threadIdx.x;
    const int wid  = tid >> 5;
    const int lane = tid & 31;
    const int gid  = lane >> 2;          // 0..7
    const int tig  = lane & 3;           // 0..3
    const int slab  = (wid & 3) << 4;    // m-slab base (0,16,32,48)
    const int nbase = (wid >> 2) << 5;   // n-group base (0,32,64,96)

    // Stage W2 (bf16 k-pairs, row kp = k/2, col n). One-time.
    for (int idx = tid; idx < 64 * D; idx += THREADS) {
        const int kp = idx >> 7, n = idx & 127;
        W2[kp * SB + n] = bfpack(w[(2 * kp) * D + n], w[(2 * kp + 1) * D + n]);
    }

    const int start   = blockIdx.x;
    const int gstride = gridDim.x;

    // Preamble: fill buffer 0 with tile `start` (also streams its y1).
    {
        const long rowbase = (long)start * TILE_M;
        #pragma unroll
        for (int p = 0; p < 4; p++) {
            const int  i = p * THREADS + tid;
            const int  r = i >> 5;
            const int  q = i & 31;
            const long g = (rowbase + r) * 256L + 4 * q;
            const float4 v = *(const float4*)(x + g);
            *(float4*)(out + g) = v;                      // y1 (exact fp32)
            XB[0][r * SA + 2 * q]     = bfpack(v.x, v.y);
            XB[0][r * SA + 2 * q + 1] = bfpack(v.z, v.w);
        }
    }
    __syncthreads();

    int buf = 0;
    for (int t = start; t < NUM_TILES; t += gstride, buf ^= 1) {
        const long rowbase = (long)t * TILE_M;
        const int  nt      = t + gstride;
        const bool hn      = nt < NUM_TILES;

        // Prefetch next tile's x1 into registers (consumed after mainloop).
        float4 pf[4];
        if (hn) {
            const long nb = (long)nt * TILE_M;
            #pragma unroll
            for (int p = 0; p < 4; p++) {
                const int i = p * THREADS + tid;
                pf[p] = *(const float4*)(x + (nb + (i >> 5)) * 256L + 4 * (i & 31));
            }
        }

        // Prefetch this tile's x2 into registers.
        const long r0 = rowbase + slab + gid;
        float2 x2a[4], x2b[4];
        #pragma unroll
        for (int j = 0; j < 4; j++) {
            const long g0 = r0 * 256L + 128 + nbase + 8 * j + 2 * tig;
            x2a[j] = *(const float2*)(x + g0);
            x2b[j] = *(const float2*)(x + g0 + 8 * 256L);
        }

        // Mainloop: 8 k-steps (K=16 each) x 4 n-tiles.
        float acc[4][4];
        #pragma unroll
        for (int j = 0; j < 4; j++)
            { acc[j][0] = 0.f; acc[j][1] = 0.f; acc[j][2] = 0.f; acc[j][3] = 0.f; }

        const uint32_t* X = XB[buf];
        const uint32_t* xr0 = X + (slab + gid) * SA;       // row gid of slab
        const uint32_t* xr1 = xr0 + 8 * SA;                // row gid+8

        #pragma unroll
        for (int ks = 0; ks < 8; ks++) {
            const int kp = ks * 8;
            const uint32_t a0 = xr0[kp + tig];
            const uint32_t a1 = xr1[kp + tig];
            const uint32_t a2 = xr0[kp + 4 + tig];
            const uint32_t a3 = xr1[kp + 4 + tig];

            const uint32_t* b0p = W2 + (kp + tig) * SB + nbase + gid;
            const uint32_t* b1p = b0p + 4 * SB;
            #pragma unroll
            for (int j = 0; j < 4; j++) {
                mma_bf16(acc[j][0], acc[j][1], acc[j][2], acc[j][3],
                         a0, a1, a2, a3, b0p[8 * j], b1p[8 * j]);
            }
        }

        // Epilogue: y2 = x2 + acc (x2 already in registers; sector-exact STG.64).
        #pragma unroll
        for (int j = 0; j < 4; j++) {
            const long g0 = r0 * 256L + 128 + nbase + 8 * j + 2 * tig;
            float2 o0, o1;
            o0.x = x2a[j].x + acc[j][0];
            o0.y = x2a[j].y + acc[j][1];
            o1.x = x2b[j].x + acc[j][2];
            o1.y = x2b[j].y + acc[j][3];
            *(float2*)(out + g0) = o0;
            *(float2*)(out + g0 + 8 * 256L) = o1;
        }

        // Drain prefetch: y1 of next tile + convert into the other buffer.
        if (hn) {
            const long nb = (long)nt * TILE_M;
            uint32_t* Xn = XB[buf ^ 1];
            #pragma unroll
            for (int p = 0; p < 4; p++) {
                const int  i = p * THREADS + tid;
                const int  r = i >> 5;
                const int  q = i & 31;
                *(float4*)(out + (nb + r) * 256L + 4 * q) = pf[p];   // y1
                Xn[r * SA + 2 * q]     = bfpack(pf[p].x, pf[p].y);
                Xn[r * SA + 2 * q + 1] = bfpack(pf[p].z, pf[p].w);
            }
        }

        __syncthreads();   // next buffer complete; current buffer reads done
    }
}

extern "C" void kernel_launch(void* const* d_in, const int* in_sizes, int n_in,
                              void* d_out, int out_size)
{
    const float* x = (const float*)d_in[0];   // [8, 32768, 256] fp32
    const float* w = (const float*)d_in[1];   // [128, 128] fp32
    float* out = (float*)d_out;

    cudaFuncSetAttribute(revnet_bf16_kernel,
                         cudaFuncAttributeMaxDynamicSharedMemorySize,
                         SMEM_BYTES);

    // 2 CTAs per SM -> independent pipelines that cover each other's stalls.
    revnet_bf16_kernel<<<296, THREADS, SMEM_BYTES>>>(x, w, out);
}